// round 1
// baseline (speedup 1.0000x reference)
#include <cuda_runtime.h>
#include <cstdint>

// InstantNGP 2D hash-grid bilinear lookup.
// x: [B,2] f32 in [0,1); table: [524288, 2] f32; out: [B,2] f32.
// idx = (c0 * 1) XOR (c1 * 2654435761) mod 2^19  — all values non-negative,
// so int64 remainder == 32-bit mask of low 19 bits.

#define RESOLUTION 1024.0f
#define TABLE_MASK 524287u
#define PI2 2654435761u

__global__ __launch_bounds__(256)
void ingp_kernel(const float2* __restrict__ x,
                 const float2* __restrict__ table,
                 float2* __restrict__ out,
                 int n)
{
    int i = blockIdx.x * blockDim.x + threadIdx.x;
    if (i >= n) return;

    float2 p = x[i];
    float xs = p.x * RESOLUTION;
    float ys = p.y * RESOLUTION;
    float fx0 = floorf(xs);
    float fy0 = floorf(ys);

    unsigned c0 = (unsigned)fx0;
    unsigned c1 = (unsigned)fy0;

    unsigned h1a = c1 * PI2;
    unsigned h1b = (c1 + 1u) * PI2;

    unsigned i00 = (c0 ^ h1a) & TABLE_MASK;          // corner (0,0)
    unsigned i01 = (c0 ^ h1b) & TABLE_MASK;          // corner (0,1)
    unsigned i10 = ((c0 + 1u) ^ h1a) & TABLE_MASK;   // corner (1,0)
    unsigned i11 = ((c0 + 1u) ^ h1b) & TABLE_MASK;   // corner (1,1)

    // Issue all 4 gathers up front for MLP.
    float2 f00 = __ldg(&table[i00]);
    float2 f01 = __ldg(&table[i01]);
    float2 f10 = __ldg(&table[i10]);
    float2 f11 = __ldg(&table[i11]);

    float fx = xs - fx0;
    float fy = ys - fy0;
    float gx = 1.0f - fx;
    float gy = 1.0f - fy;

    float w00 = gx * gy;
    float w01 = gx * fy;
    float w10 = fx * gy;
    float w11 = fx * fy;

    float2 o;
    o.x = f00.x * w00 + f01.x * w01 + f10.x * w10 + f11.x * w11;
    o.y = f00.y * w00 + f01.y * w01 + f10.y * w10 + f11.y * w11;
    out[i] = o;
}

extern "C" void kernel_launch(void* const* d_in, const int* in_sizes, int n_in,
                              void* d_out, int out_size)
{
    const float2* x     = (const float2*)d_in[0];   // [B,2] f32
    const float2* table = (const float2*)d_in[1];   // [524288,2] f32
    float2* out         = (float2*)d_out;

    int n = in_sizes[0] / 2;  // number of points
    int threads = 256;
    int blocks = (n + threads - 1) / threads;
    ingp_kernel<<<blocks, threads>>>(x, table, out, n);
}

// round 2
// speedup vs baseline: 1.0437x; 1.0437x over previous
#include <cuda_runtime.h>
#include <cstdint>

// InstantNGP 2D hash-grid bilinear lookup, gather-merged version.
// Hash: idx = c0 ^ (PI2*c1) & (2^19-1). Corners (c0, c0+1) at fixed c1 map to
// indices c0^h and (c0+1)^h. The float4 (16B) at table index (c0^h)>>1 covers
// table entries {(c0^h)&~1, (c0^h)|1} = corners {c0, c0^1}:
//   c0 even -> {c0, c0+1}: BOTH corners in one LDG.128.
//   c0 odd  -> {c0-1, c0}: only corner c0; a second predicated LDG.128 at
//              ((c0+1)^h)>>1 fetches corner c0+1.

#define RESOLUTION 1024.0f
#define TABLE_MASK 524287u
#define PI2 2654435761u

__device__ __forceinline__ float2 sel_half(float4 v, unsigned bit) {
    return bit ? make_float2(v.z, v.w) : make_float2(v.x, v.y);
}

__global__ __launch_bounds__(256)
void ingp_kernel(const float2* __restrict__ x,
                 const float4* __restrict__ table4,
                 float2* __restrict__ out,
                 int n)
{
    int i = blockIdx.x * blockDim.x + threadIdx.x;
    if (i >= n) return;

    float2 p = x[i];
    float xs = p.x * RESOLUTION;
    float ys = p.y * RESOLUTION;
    float fx0 = floorf(xs);
    float fy0 = floorf(ys);

    unsigned c0 = (unsigned)fx0;
    unsigned c1 = (unsigned)fy0;
    unsigned c0o = c0 & 1u;         // parity of x-corner

    unsigned ha = c1 * PI2;         // row a: y = c1
    unsigned hb = ha + PI2;         // row b: y = c1+1

    unsigned ia = (c0 ^ ha) & TABLE_MASK;          // corner (c0,   c1)
    unsigned ja = ((c0 + 1u) ^ ha) & TABLE_MASK;   // corner (c0+1, c1)
    unsigned ib = (c0 ^ hb) & TABLE_MASK;          // corner (c0,   c1+1)
    unsigned jb = ((c0 + 1u) ^ hb) & TABLE_MASK;   // corner (c0+1, c1+1)

    // Primary pair loads: always cover corner c0 (and c0+1 too when c0 even).
    float4 A0 = __ldg(&table4[ia >> 1]);
    float4 B0 = __ldg(&table4[ib >> 1]);

    // Secondary loads only needed when c0 is odd (predicated LDG.128).
    float4 A1 = make_float4(0.f, 0.f, 0.f, 0.f);
    float4 B1 = make_float4(0.f, 0.f, 0.f, 0.f);
    if (c0o) {
        A1 = __ldg(&table4[ja >> 1]);
        B1 = __ldg(&table4[jb >> 1]);
    }

    float2 f00 = sel_half(A0, ia & 1u);
    float2 f01 = sel_half(B0, ib & 1u);
    float2 f10 = c0o ? sel_half(A1, ja & 1u) : sel_half(A0, (ia & 1u) ^ 1u);
    float2 f11 = c0o ? sel_half(B1, jb & 1u) : sel_half(B0, (ib & 1u) ^ 1u);

    float fx = xs - fx0;
    float fy = ys - fy0;
    float gx = 1.0f - fx;
    float gy = 1.0f - fy;

    float w00 = gx * gy;
    float w01 = gx * fy;
    float w10 = fx * gy;
    float w11 = fx * fy;

    float2 o;
    o.x = f00.x * w00 + f01.x * w01 + f10.x * w10 + f11.x * w11;
    o.y = f00.y * w00 + f01.y * w01 + f10.y * w10 + f11.y * w11;
    out[i] = o;
}

extern "C" void kernel_launch(void* const* d_in, const int* in_sizes, int n_in,
                              void* d_out, int out_size)
{
    const float2* x      = (const float2*)d_in[0];   // [B,2] f32
    const float4* table4 = (const float4*)d_in[1];   // [524288,2] f32 viewed as float4 pairs
    float2* out          = (float2*)d_out;

    int n = in_sizes[0] / 2;  // number of points
    int threads = 256;
    int blocks = (n + threads - 1) / threads;
    ingp_kernel<<<blocks, threads>>>(x, table4, out, n);
}